// round 9
// baseline (speedup 1.0000x reference)
#include <cuda_runtime.h>
#include <cuda_bf16.h>
#include <math.h>

#define BATCH 2
#define SEQ   2048
#define DMODEL 1024
#define NHEADS 16
#define DHEAD  64
#define MROWS (BATCH*SEQ)                    // 4096
#define ATT_OFF ((size_t)BATCH*SEQ*DMODEL)
#define NKT 16                               // key tiles (128 each)
#define VPSTG 4

// gq, gk, gv, gctx, go
__device__ float g_scratch[5ull * MROWS * DMODEL];

// vproj/oproj dynamic smem: A + W stages [4][128][20] each
#define VP_AS   (VPSTG * 128 * 20)
#define VP_SMEM (2 * VP_AS * 4)

// attn_fused smem (u32 words):
//  Qh/Ql [64][36], Kh/Kl [128][36], Pb [64][68], Vb [64][68], ssum[4][64], invs[64]
#define AT_WORDS (2*64*36 + 2*128*36 + 64*68 + 64*68 + 256 + 64)
#define AT_SMEM  (AT_WORDS * 4)

// ---------------------------------------------------------------------------
__device__ __forceinline__ unsigned f2tf(float x) {
    unsigned r;
    asm("cvt.rna.tf32.f32 %0, %1;" : "=r"(r) : "f"(x));
    return r;
}
__device__ __forceinline__ void mma8(float* d, const unsigned* a, const unsigned* b) {
    asm volatile(
        "mma.sync.aligned.m16n8k8.row.col.f32.tf32.tf32.f32 "
        "{%0,%1,%2,%3}, {%4,%5,%6,%7}, {%8,%9}, {%0,%1,%2,%3};"
        : "+f"(d[0]), "+f"(d[1]), "+f"(d[2]), "+f"(d[3])
        : "r"(a[0]), "r"(a[1]), "r"(a[2]), "r"(a[3]), "r"(b[0]), "r"(b[1]));
}
__device__ __forceinline__ void mma16(float* d, const unsigned* a, const unsigned* b) {
    asm volatile(
        "mma.sync.aligned.m16n8k16.row.col.f32.bf16.bf16.f32 "
        "{%0,%1,%2,%3}, {%4,%5,%6,%7}, {%8,%9}, {%0,%1,%2,%3};"
        : "+f"(d[0]), "+f"(d[1]), "+f"(d[2]), "+f"(d[3])
        : "r"(a[0]), "r"(a[1]), "r"(a[2]), "r"(a[3]), "r"(b[0]), "r"(b[1]));
}
__device__ __forceinline__ void splitbf2(float x, float y, unsigned& hi, unsigned& lo) {
    __nv_bfloat16 hx = __float2bfloat16_rn(x);
    __nv_bfloat16 hy = __float2bfloat16_rn(y);
    __nv_bfloat16 lx = __float2bfloat16_rn(x - __bfloat162float(hx));
    __nv_bfloat16 ly = __float2bfloat16_rn(y - __bfloat162float(hy));
    hi = (unsigned)__bfloat16_as_ushort(hx) | ((unsigned)__bfloat16_as_ushort(hy) << 16);
    lo = (unsigned)__bfloat16_as_ushort(lx) | ((unsigned)__bfloat16_as_ushort(ly) << 16);
}
__device__ __forceinline__ unsigned packbf2(float x, float y) {
    __nv_bfloat162 t = __floats2bfloat162_rn(x, y);
    return *reinterpret_cast<unsigned*>(&t);
}
__device__ __forceinline__ void cpasync16(void* sm, const void* gm) {
    unsigned a = (unsigned)__cvta_generic_to_shared(sm);
    asm volatile("cp.async.cg.shared.global [%0], [%1], 16;" :: "r"(a), "l"(gm));
}

// ---------------------------------------------------------------------------
// NT GEMM + bias (1xTF32), cp.async 4-stage pipeline (v projection + o proj).
// ---------------------------------------------------------------------------
__global__ __launch_bounds__(256, 2)
void gemm_nt_tf32(const float* __restrict__ A, const float* __restrict__ W,
                  const float* __restrict__ bias, float* __restrict__ C) {
    extern __shared__ float vsm[];
    float* As2 = vsm;              // [VPSTG][128][20]
    float* Ws2 = vsm + VP_AS;      // [VPSTG][128][20]
    const int tid = threadIdx.x, lane = tid & 31, warp = tid >> 5;
    const int wm = (warp & 3) * 32, wn = (warp >> 2) * 64;
    const int row0 = blockIdx.y * 128, col0 = blockIdx.x * 128;
    const int ntiles = DMODEL / 16;

    auto prefetch = [&](int t) {
        int s = t & (VPSTG - 1);
        int k0 = t * 16;
        #pragma unroll
        for (int l = 0; l < 2; l++) {
            int c = tid + l * 256, r = c >> 2, qd = (c & 3) * 4;
            cpasync16(&As2[s*2560 + r*20 + qd], &A[(size_t)(row0+r)*DMODEL + k0 + qd]);
            cpasync16(&Ws2[s*2560 + r*20 + qd], &W[(size_t)(col0+r)*DMODEL + k0 + qd]);
        }
        asm volatile("cp.async.commit_group;");
    };
    #pragma unroll
    for (int t = 0; t < VPSTG - 1; t++) prefetch(t);

    float acc[2][8][4] = {};
    for (int t = 0; t < ntiles; t++) {
        int s = t & (VPSTG - 1);
        asm volatile("cp.async.wait_group %0;" :: "n"(VPSTG - 2));
        __syncthreads();
        const float* Ap = &As2[s*2560];
        const float* Wp = &Ws2[s*2560];
        #pragma unroll
        for (int kk = 0; kk < 16; kk += 8) {
            const int kr = kk + (lane & 3), m0 = wm + (lane >> 2);
            unsigned af[2][4];
            #pragma unroll
            for (int i = 0; i < 2; i++) {
                af[i][0] = __float_as_uint(Ap[(m0+i*16)*20 + kr]);
                af[i][1] = __float_as_uint(Ap[(m0+i*16+8)*20 + kr]);
                af[i][2] = __float_as_uint(Ap[(m0+i*16)*20 + kr+4]);
                af[i][3] = __float_as_uint(Ap[(m0+i*16+8)*20 + kr+4]);
            }
            #pragma unroll
            for (int j = 0; j < 8; j++) {
                int nb = wn + j * 8 + (lane >> 2);
                unsigned bf[2] = {__float_as_uint(Wp[nb*20 + kr]),
                                  __float_as_uint(Wp[nb*20 + kr+4])};
                mma8(acc[0][j], af[0], bf);
                mma8(acc[1][j], af[1], bf);
            }
        }
        __syncthreads();
        if (t + VPSTG - 1 < ntiles) prefetch(t + VPSTG - 1);
        else asm volatile("cp.async.commit_group;");
    }
    #pragma unroll
    for (int j = 0; j < 8; j++) {
        int c = col0 + wn + j * 8 + (lane & 3) * 2;
        float2 bb = *(const float2*)&bias[c];
        #pragma unroll
        for (int i = 0; i < 2; i++) {
            size_t r = row0 + wm + i * 16 + (lane >> 2);
            float2 o0 = {acc[i][j][0] + bb.x, acc[i][j][1] + bb.y};
            float2 o1 = {acc[i][j][2] + bb.x, acc[i][j][3] + bb.y};
            *(float2*)&C[r * DMODEL + c]       = o0;
            *(float2*)&C[(r + 8) * DMODEL + c] = o1;
        }
    }
}

// ---------------------------------------------------------------------------
// q+k projections, 3xBF16 split, register-pipelined, batched on blockIdx.z.
// ---------------------------------------------------------------------------
__global__ __launch_bounds__(256, 2)
void gemm_qk_bf16x3(const float* __restrict__ qin, const float* __restrict__ kin,
                    const float* __restrict__ wq, const float* __restrict__ wk,
                    const float* __restrict__ bq, const float* __restrict__ bk,
                    float* __restrict__ gq, float* __restrict__ gk) {
    const float* A    = blockIdx.z ? kin : qin;
    const float* W    = blockIdx.z ? wk  : wq;
    const float* bias = blockIdx.z ? bk  : bq;
    float* C          = blockIdx.z ? gk  : gq;

    __shared__ unsigned Ah2[2][8][132], Al2[2][8][132];
    __shared__ unsigned Bh2[2][8][132], Bl2[2][8][132];
    const int tid = threadIdx.x, lane = tid & 31, warp = tid >> 5;
    const int wm = (warp & 3) * 32, wn = (warp >> 2) * 64;
    const int row0 = blockIdx.y * 128, col0 = blockIdx.x * 128;
    const int kq = lane & 3;

    float4 ra[2], rb[2];
    auto doload = [&](int k0) {
        #pragma unroll
        for (int l = 0; l < 2; l++) {
            int idx = tid + l * 256, r = idx >> 2, kc = (idx & 3) << 2;
            ra[l] = *(const float4*)&A[(size_t)(row0 + r) * DMODEL + k0 + kc];
            rb[l] = *(const float4*)&W[(size_t)(col0 + r) * DMODEL + k0 + kc];
        }
    };
    auto dostore = [&](int bf) {
        #pragma unroll
        for (int l = 0; l < 2; l++) {
            int idx = tid + l * 256, r = idx >> 2, kc = (idx & 3) << 2, kp = kc >> 1;
            unsigned h0, l0, h1, l1;
            splitbf2(ra[l].x, ra[l].y, h0, l0); splitbf2(ra[l].z, ra[l].w, h1, l1);
            Ah2[bf][kp][r] = h0; Ah2[bf][kp+1][r] = h1;
            Al2[bf][kp][r] = l0; Al2[bf][kp+1][r] = l1;
            splitbf2(rb[l].x, rb[l].y, h0, l0); splitbf2(rb[l].z, rb[l].w, h1, l1);
            Bh2[bf][kp][r] = h0; Bh2[bf][kp+1][r] = h1;
            Bl2[bf][kp][r] = l0; Bl2[bf][kp+1][r] = l1;
        }
    };

    float acc[2][8][4] = {};
    doload(0); dostore(0); __syncthreads();
    int bf = 0;
    for (int k0 = 0; k0 < DMODEL; k0 += 16) {
        bool more = (k0 + 16 < DMODEL);
        if (more) doload(k0 + 16);
        unsigned ah[2][4], al[2][4];
        #pragma unroll
        for (int i = 0; i < 2; i++) {
            int m0 = wm + i * 16 + (lane >> 2);
            ah[i][0]=Ah2[bf][kq][m0];   ah[i][1]=Ah2[bf][kq][m0+8];
            ah[i][2]=Ah2[bf][kq+4][m0]; ah[i][3]=Ah2[bf][kq+4][m0+8];
            al[i][0]=Al2[bf][kq][m0];   al[i][1]=Al2[bf][kq][m0+8];
            al[i][2]=Al2[bf][kq+4][m0]; al[i][3]=Al2[bf][kq+4][m0+8];
        }
        #pragma unroll
        for (int j = 0; j < 8; j++) {
            int nb = wn + j * 8 + (lane >> 2);
            unsigned bh2[2] = {Bh2[bf][kq][nb], Bh2[bf][kq+4][nb]};
            unsigned bl2[2] = {Bl2[bf][kq][nb], Bl2[bf][kq+4][nb]};
            #pragma unroll
            for (int i = 0; i < 2; i++) {
                mma16(acc[i][j], al[i], bh2);
                mma16(acc[i][j], ah[i], bl2);
                mma16(acc[i][j], ah[i], bh2);
            }
        }
        if (more) { dostore(bf ^ 1); __syncthreads(); bf ^= 1; }
    }
    #pragma unroll
    for (int j = 0; j < 8; j++) {
        int c = col0 + wn + j * 8 + (lane & 3) * 2;
        float2 bb = *(const float2*)&bias[c];
        #pragma unroll
        for (int i = 0; i < 2; i++) {
            size_t r = row0 + wm + i * 16 + (lane >> 2);
            float2 o0 = {acc[i][j][0] + bb.x, acc[i][j][1] + bb.y};
            float2 o1 = {acc[i][j][2] + bb.x, acc[i][j][3] + bb.y};
            *(float2*)&C[r * DMODEL + c]       = o0;
            *(float2*)&C[(r + 8) * DMODEL + c] = o1;
        }
    }
}

// ---------------------------------------------------------------------------
// Fused attention: one CTA per (bh, 64-row q-tile).
// Pass A: S=QK^T (3xbf16) -> exp (masked, unnormalized) -> rowsums + PV
//         (bf16 mma via smem-staged P k-pairs). No P write.
// Then: inv_s from own rowsums; write ctx*inv_s.
// Pass B: recompute S (identical), exp * inv_s, write normalized P once.
// grid (32 bh fastest, 32 qtile), 256 threads, warps 2(M)x4(N).
// ---------------------------------------------------------------------------
__global__ __launch_bounds__(256, 2)
void attn_fused(const float* __restrict__ gq, const float* __restrict__ gk,
                const float* __restrict__ gv, const int* __restrict__ mask,
                float* __restrict__ attn, float* __restrict__ gctx) {
    extern __shared__ unsigned smw[];
    unsigned* Qh = smw;                    // [64][36] row x kpair
    unsigned* Ql = Qh + 64*36;
    unsigned* Kh = Ql + 64*36;             // [128][36] key x kpair
    unsigned* Kl = Kh + 128*36;
    unsigned* Pb = Kl + 128*36;            // [64][68] qrow x keypair (bf16x2)
    unsigned* Vb = Pb + 64*68;             // [64][68] keypair x ncol (bf16x2)
    float* ssum  = (float*)(Vb + 64*68);   // [4][64]
    float* invs  = ssum + 256;             // [64]

    const int tid = threadIdx.x, lane = tid & 31, warp = tid >> 5;
    const int wm = (warp & 1) * 32;        // M warp (2)
    const int wn = (warp >> 1) * 32;       // N warp (4) over 128 keys
    const int kq = lane & 3;
    const int bh = blockIdx.x, b = bh >> 4, h = bh & 15;
    const int q0 = blockIdx.y * 64;
    const float* Qg = gq + (size_t)b * SEQ * DMODEL + h * DHEAD;
    const float* Kg = gk + (size_t)b * SEQ * DMODEL + h * DHEAD;
    const float* Vg = gv + (size_t)b * SEQ * DMODEL + h * DHEAD;
    const int* mrow = mask + (size_t)b * SEQ * SEQ;
    float* Pout = attn + (size_t)bh * SEQ * SEQ;

    // Load Q strip (64x64) split into bf16 hi/lo
    #pragma unroll
    for (int l = 0; l < 4; l++) {
        int idx = tid + l * 256, r = idx >> 4, kc = (idx & 15) << 2, kp = kc >> 1;
        float4 a4 = *(const float4*)&Qg[(size_t)(q0 + r) * DMODEL + kc];
        unsigned h0, l0, h1, l1;
        splitbf2(a4.x, a4.y, h0, l0); splitbf2(a4.z, a4.w, h1, l1);
        Qh[r*36 + kp] = h0; Qh[r*36 + kp + 1] = h1;
        Ql[r*36 + kp] = l0; Ql[r*36 + kp + 1] = l1;
    }

    auto fillK = [&](int c0) {
        #pragma unroll
        for (int l = 0; l < 8; l++) {
            int idx = tid + l * 256, r = idx >> 4, kc = (idx & 15) << 2, kp = kc >> 1;
            float4 b4 = *(const float4*)&Kg[(size_t)(c0 + r) * DMODEL + kc];
            unsigned h0, l0, h1, l1;
            splitbf2(b4.x, b4.y, h0, l0); splitbf2(b4.z, b4.w, h1, l1);
            Kh[r*36 + kp] = h0; Kh[r*36 + kp + 1] = h1;
            Kl[r*36 + kp] = l0; Kl[r*36 + kp + 1] = l1;
        }
    };

    auto computeS = [&](float (&acc)[2][4][4]) {
        #pragma unroll
        for (int kk = 0; kk < 32; kk += 8) {
            unsigned ah[2][4], al[2][4];
            #pragma unroll
            for (int i = 0; i < 2; i++) {
                int m0 = wm + i * 16 + (lane >> 2);
                ah[i][0] = Qh[m0*36 + kk+kq];       ah[i][1] = Qh[(m0+8)*36 + kk+kq];
                ah[i][2] = Qh[m0*36 + kk+kq+4];     ah[i][3] = Qh[(m0+8)*36 + kk+kq+4];
                al[i][0] = Ql[m0*36 + kk+kq];       al[i][1] = Ql[(m0+8)*36 + kk+kq];
                al[i][2] = Ql[m0*36 + kk+kq+4];     al[i][3] = Ql[(m0+8)*36 + kk+kq+4];
            }
            #pragma unroll
            for (int j = 0; j < 4; j++) {
                int nb = wn + j * 8 + (lane >> 2);
                unsigned bh2[2] = {Kh[nb*36 + kk+kq], Kh[nb*36 + kk+kq+4]};
                unsigned bl2[2] = {Kl[nb*36 + kk+kq], Kl[nb*36 + kk+kq+4]};
                #pragma unroll
                for (int i = 0; i < 2; i++) {
                    mma16(acc[i][j], al[i], bh2);
                    mma16(acc[i][j], ah[i], bl2);
                    mma16(acc[i][j], ah[i], bh2);
                }
            }
        }
    };

    float rs[2][2] = {};
    float accpv[2][2][4] = {};

    // ---------------- Pass A: rowsums + PV ----------------
    for (int kt = 0; kt < NKT; kt++) {
        const int c0 = kt * 128;
        __syncthreads();            // smem safe to overwrite
        fillK(c0);
        #pragma unroll
        for (int l = 0; l < 4; l++) {   // V tile -> bf16x2 k-pairs
            int idx = tid + l * 256, kp = idx >> 4, n4 = (idx & 15) << 2;
            const float* vp0 = &Vg[(size_t)(c0 + kp * 2) * DMODEL + n4];
            float4 v0 = *(const float4*)vp0;
            float4 v1 = *(const float4*)(vp0 + DMODEL);
            uint4 pk;
            pk.x = packbf2(v0.x, v1.x); pk.y = packbf2(v0.y, v1.y);
            pk.z = packbf2(v0.z, v1.z); pk.w = packbf2(v0.w, v1.w);
            *(uint4*)&Vb[kp*68 + n4] = pk;
        }
        __syncthreads();
        float acc[2][4][4] = {};
        computeS(acc);
        // mask -> exp -> rowsums + stage P (bf16x2 along key pairs)
        #pragma unroll
        for (int j = 0; j < 4; j++) {
            int cl = wn + j * 8 + (lane & 3) * 2;
            int kp_l = cl >> 1;
            #pragma unroll
            for (int i = 0; i < 2; i++) {
                int r0 = wm + i * 16 + (lane >> 2);
                size_t rg = q0 + r0;
                int2 m0v = *(const int2*)&mrow[rg * SEQ + c0 + cl];
                int2 m1v = *(const int2*)&mrow[(rg + 8) * SEQ + c0 + cl];
                float p00 = m0v.x ? __expf(acc[i][j][0] * 0.125f) : 0.f;
                float p01 = m0v.y ? __expf(acc[i][j][1] * 0.125f) : 0.f;
                float p10 = m1v.x ? __expf(acc[i][j][2] * 0.125f) : 0.f;
                float p11 = m1v.y ? __expf(acc[i][j][3] * 0.125f) : 0.f;
                rs[i][0] += p00 + p01;
                rs[i][1] += p10 + p11;
                Pb[r0*68 + kp_l]       = packbf2(p00, p01);
                Pb[(r0 + 8)*68 + kp_l] = packbf2(p10, p11);
            }
        }
        __syncthreads();            // Pb/Vb visible
        // PV: ctx += P(bf16) @ V(bf16), contraction over this ktile's 128 keys
        #pragma unroll
        for (int kkp = 0; kkp < 64; kkp += 8) {
            unsigned pa[2][4];
            #pragma unroll
            for (int i = 0; i < 2; i++) {
                int m0 = wm + i * 16 + (lane >> 2);
                pa[i][0] = Pb[m0*68 + kkp+kq];     pa[i][1] = Pb[(m0+8)*68 + kkp+kq];
                pa[i][2] = Pb[m0*68 + kkp+kq+4];   pa[i][3] = Pb[(m0+8)*68 + kkp+kq+4];
            }
            #pragma unroll
            for (int j = 0; j < 2; j++) {
                int n = (warp >> 1) * 16 + j * 8 + (lane >> 2);
                unsigned vb2[2] = {Vb[(kkp+kq)*68 + n], Vb[(kkp+kq+4)*68 + n]};
                mma16(accpv[0][j], pa[0], vb2);
                mma16(accpv[1][j], pa[1], vb2);
            }
        }
    }

    // ---------------- rowsum reduction -> inv_s ----------------
    #pragma unroll
    for (int i = 0; i < 2; i++)
        #pragma unroll
        for (int hh = 0; hh < 2; hh++) {
            float v = rs[i][hh];
            v += __shfl_xor_sync(0xffffffffu, v, 1);
            v += __shfl_xor_sync(0xffffffffu, v, 2);
            if ((lane & 3) == 0)
                ssum[(warp >> 1) * 64 + wm + i * 16 + hh * 8 + (lane >> 2)] = v;
        }
    __syncthreads();
    if (tid < 64)
        invs[tid] = 1.0f / (ssum[tid] + ssum[64 + tid] + ssum[128 + tid] + ssum[192 + tid]);
    __syncthreads();

    // ---------------- write ctx * inv_s ----------------
    {
        float* Cg = gctx + (size_t)b * SEQ * DMODEL + h * DHEAD;
        #pragma unroll
        for (int i = 0; i < 2; i++) {
            int r0 = wm + i * 16 + (lane >> 2);
            float sc0 = invs[r0], sc1 = invs[r0 + 8];
            #pragma unroll
            for (int j = 0; j < 2; j++) {
                int nW = (warp >> 1) * 16 + j * 8 + (lane & 3) * 2;
                float2 o0 = {accpv[i][j][0] * sc0, accpv[i][j][1] * sc0};
                float2 o1 = {accpv[i][j][2] * sc1, accpv[i][j][3] * sc1};
                *(float2*)&Cg[(size_t)(q0 + r0) * DMODEL + nW]     = o0;
                *(float2*)&Cg[(size_t)(q0 + r0 + 8) * DMODEL + nW] = o1;
            }
        }
    }

    // ---------------- Pass B: recompute S, write normalized P ----------------
    for (int kt = 0; kt < NKT; kt++) {
        const int c0 = kt * 128;
        __syncthreads();
        fillK(c0);
        __syncthreads();
        float acc[2][4][4] = {};
        computeS(acc);
        #pragma unroll
        for (int j = 0; j < 4; j++) {
            int cl = wn + j * 8 + (lane & 3) * 2;
            #pragma unroll
            for (int i = 0; i < 2; i++) {
                int r0 = wm + i * 16 + (lane >> 2);
                size_t rg = q0 + r0;
                float sc0 = invs[r0], sc1 = invs[r0 + 8];
                int2 m0v = *(const int2*)&mrow[rg * SEQ + c0 + cl];
                int2 m1v = *(const int2*)&mrow[(rg + 8) * SEQ + c0 + cl];
                float2 o0, o1;
                o0.x = m0v.x ? __expf(acc[i][j][0] * 0.125f) * sc0 : 0.f;
                o0.y = m0v.y ? __expf(acc[i][j][1] * 0.125f) * sc0 : 0.f;
                o1.x = m1v.x ? __expf(acc[i][j][2] * 0.125f) * sc1 : 0.f;
                o1.y = m1v.y ? __expf(acc[i][j][3] * 0.125f) * sc1 : 0.f;
                *(float2*)&Pout[rg * SEQ + c0 + cl]       = o0;
                *(float2*)&Pout[(rg + 8) * SEQ + c0 + cl] = o1;
            }
        }
    }
}

// ---------------------------------------------------------------------------
// Residual + LayerNorm.
// ---------------------------------------------------------------------------
__global__ void ln_kernel(const float* __restrict__ resid,
                          const float* __restrict__ x,
                          const float* __restrict__ gamma,
                          const float* __restrict__ beta,
                          float* __restrict__ out) {
    const size_t row = blockIdx.x;
    const float4* xr = reinterpret_cast<const float4*>(x + row * DMODEL);
    const float4* rr = reinterpret_cast<const float4*>(resid + row * DMODEL);
    const int t = threadIdx.x;
    __shared__ float sred[8];

    float4 a = rr[t], bv = xr[t];
    float4 v = {a.x + bv.x, a.y + bv.y, a.z + bv.z, a.w + bv.w};
    float s = v.x + v.y + v.z + v.w;
    #pragma unroll
    for (int o = 16; o > 0; o >>= 1) s += __shfl_xor_sync(0xffffffffu, s, o);
    if ((t & 31) == 0) sred[t >> 5] = s;
    __syncthreads();
    float tot = 0.f;
    #pragma unroll
    for (int i = 0; i < 8; i++) tot += sred[i];
    const float mu = tot * (1.0f / DMODEL);
    __syncthreads();

    float dx = v.x - mu, dy = v.y - mu, dz = v.z - mu, dw = v.w - mu;
    float sq = dx*dx + dy*dy + dz*dz + dw*dw;
    #pragma unroll
    for (int o = 16; o > 0; o >>= 1) sq += __shfl_xor_sync(0xffffffffu, sq, o);
    if ((t & 31) == 0) sred[t >> 5] = sq;
    __syncthreads();
    float tot2 = 0.f;
    #pragma unroll
    for (int i = 0; i < 8; i++) tot2 += sred[i];
    const float inv = rsqrtf(tot2 * (1.0f / DMODEL) + 1e-5f);

    float4 g = reinterpret_cast<const float4*>(gamma)[t];
    float4 be = reinterpret_cast<const float4*>(beta)[t];
    float4 o;
    o.x = dx * inv * g.x + be.x;
    o.y = dy * inv * g.y + be.y;
    o.z = dz * inv * g.z + be.z;
    o.w = dw * inv * g.w + be.w;
    reinterpret_cast<float4*>(out + row * DMODEL)[t] = o;
}

// ---------------------------------------------------------------------------
extern "C" void kernel_launch(void* const* d_in, const int* in_sizes, int n_in,
                              void* d_out, int out_size) {
    const float* q     = (const float*)d_in[0];
    const float* k     = (const float*)d_in[1];
    const float* v     = (const float*)d_in[2];
    const int*   mask  = (const int*)  d_in[3];
    const float* wq    = (const float*)d_in[4];
    const float* bq    = (const float*)d_in[5];
    const float* wk    = (const float*)d_in[6];
    const float* bk    = (const float*)d_in[7];
    const float* wv    = (const float*)d_in[8];
    const float* bv    = (const float*)d_in[9];
    const float* wo    = (const float*)d_in[10];
    const float* bo    = (const float*)d_in[11];
    const float* gamma = (const float*)d_in[12];
    const float* beta  = (const float*)d_in[13];

    float* out  = (float*)d_out;
    float* attn = out + ATT_OFF;

    void* sp = nullptr;
    cudaGetSymbolAddress(&sp, g_scratch);
    const size_t PS = (size_t)MROWS * DMODEL;
    float* gq   = (float*)sp;
    float* gk   = gq + PS;
    float* gv   = gk + PS;
    float* gctx = gv + PS;
    float* go   = gctx + PS;

    cudaFuncSetAttribute(gemm_nt_tf32, cudaFuncAttributeMaxDynamicSharedMemorySize, VP_SMEM);
    cudaFuncSetAttribute(attn_fused,   cudaFuncAttributeMaxDynamicSharedMemorySize, AT_SMEM);

    dim3 gQK(DMODEL / 128, MROWS / 128, 2);             // (8, 32, 2)
    gemm_qk_bf16x3<<<gQK, 256>>>(q, k, wq, wk, bq, bk, gq, gk);

    dim3 gProj(DMODEL / 128, MROWS / 128);              // (8, 32)
    gemm_nt_tf32<<<gProj, 256, VP_SMEM>>>(v, wv, bv, gv);

    dim3 gAT(BATCH * NHEADS, SEQ / 64);                 // (32, 32), bh fastest
    attn_fused<<<gAT, 256, AT_SMEM>>>(gq, gk, gv, mask, attn, gctx);

    gemm_nt_tf32<<<gProj, 256, VP_SMEM>>>(gctx, wo, bo, go);

    ln_kernel<<<MROWS, 256>>>(q, go, gamma, beta, out);
}

// round 10
// speedup vs baseline: 1.0904x; 1.0904x over previous
#include <cuda_runtime.h>
#include <cuda_bf16.h>
#include <math.h>

#define BATCH 2
#define SEQ   2048
#define DMODEL 1024
#define NHEADS 16
#define DHEAD  64
#define MROWS (BATCH*SEQ)                    // 4096
#define ATT_OFF ((size_t)BATCH*SEQ*DMODEL)
#define NKT 16                               // key tiles in scores grid
#define SPLITK 2                             // pv split-K factor
#define PVSTG 3
#define VPSTG 4
#define OPSTG 3

// gq, gk, gv, go (4 x PS) + pctx (2 x PS) + rowsum partials
__device__ float g_scratch[6ull * MROWS * DMODEL + (size_t)BATCH * NHEADS * SEQ * NKT];

// scores_exp dynamic smem: 4 strip arrays [32][132] u32 + sums [2][128]
#define SC_SMEM (4 * 32 * 132 * 4 + 2 * 128 * 4)
// pv dynamic smem: P stages [3][128][20] + V stages [3][16][72] + inv_s[128]
#define PV_PS   (PVSTG * 128 * 20)
#define PV_VS   (PVSTG * 16 * 72)
#define PV_SMEM ((PV_PS + PV_VS + 128) * 4)
// vproj dynamic smem: A + W stages [4][128][20] each
#define VP_AS   (VPSTG * 128 * 20)
#define VP_SMEM (2 * VP_AS * 4)
// oproj dynamic smem: 3 streams (pctx0, pctx1, W) x OPSTG stages x [128][20]
#define OP_AS   (OPSTG * 128 * 20)
#define OP_SMEM (3 * OP_AS * 4)

// ---------------------------------------------------------------------------
__device__ __forceinline__ unsigned f2tf(float x) {
    unsigned r;
    asm("cvt.rna.tf32.f32 %0, %1;" : "=r"(r) : "f"(x));
    return r;
}
__device__ __forceinline__ void mma8(float* d, const unsigned* a, const unsigned* b) {
    asm volatile(
        "mma.sync.aligned.m16n8k8.row.col.f32.tf32.tf32.f32 "
        "{%0,%1,%2,%3}, {%4,%5,%6,%7}, {%8,%9}, {%0,%1,%2,%3};"
        : "+f"(d[0]), "+f"(d[1]), "+f"(d[2]), "+f"(d[3])
        : "r"(a[0]), "r"(a[1]), "r"(a[2]), "r"(a[3]), "r"(b[0]), "r"(b[1]));
}
__device__ __forceinline__ void mma16(float* d, const unsigned* a, const unsigned* b) {
    asm volatile(
        "mma.sync.aligned.m16n8k16.row.col.f32.bf16.bf16.f32 "
        "{%0,%1,%2,%3}, {%4,%5,%6,%7}, {%8,%9}, {%0,%1,%2,%3};"
        : "+f"(d[0]), "+f"(d[1]), "+f"(d[2]), "+f"(d[3])
        : "r"(a[0]), "r"(a[1]), "r"(a[2]), "r"(a[3]), "r"(b[0]), "r"(b[1]));
}
__device__ __forceinline__ void splitbf2(float x, float y, unsigned& hi, unsigned& lo) {
    __nv_bfloat16 hx = __float2bfloat16_rn(x);
    __nv_bfloat16 hy = __float2bfloat16_rn(y);
    __nv_bfloat16 lx = __float2bfloat16_rn(x - __bfloat162float(hx));
    __nv_bfloat16 ly = __float2bfloat16_rn(y - __bfloat162float(hy));
    hi = (unsigned)__bfloat16_as_ushort(hx) | ((unsigned)__bfloat16_as_ushort(hy) << 16);
    lo = (unsigned)__bfloat16_as_ushort(lx) | ((unsigned)__bfloat16_as_ushort(ly) << 16);
}
__device__ __forceinline__ void cpasync16(void* sm, const void* gm) {
    unsigned a = (unsigned)__cvta_generic_to_shared(sm);
    asm volatile("cp.async.cg.shared.global [%0], [%1], 16;" :: "r"(a), "l"(gm));
}

// ---------------------------------------------------------------------------
// V projection (1xTF32), cp.async 4-stage pipeline, raw fp32 smem tiles.
// ---------------------------------------------------------------------------
__global__ __launch_bounds__(256, 2)
void gemm_nt_tf32(const float* __restrict__ A, const float* __restrict__ W,
                  const float* __restrict__ bias, float* __restrict__ C) {
    extern __shared__ float vsm[];
    float* As2 = vsm;              // [VPSTG][128][20]
    float* Ws2 = vsm + VP_AS;      // [VPSTG][128][20]
    const int tid = threadIdx.x, lane = tid & 31, warp = tid >> 5;
    const int wm = (warp & 3) * 32, wn = (warp >> 2) * 64;
    const int row0 = blockIdx.y * 128, col0 = blockIdx.x * 128;
    const int ntiles = DMODEL / 16;

    auto prefetch = [&](int t) {
        int s = t & (VPSTG - 1);
        int k0 = t * 16;
        #pragma unroll
        for (int l = 0; l < 2; l++) {
            int c = tid + l * 256, r = c >> 2, qd = (c & 3) * 4;
            cpasync16(&As2[s*2560 + r*20 + qd], &A[(size_t)(row0+r)*DMODEL + k0 + qd]);
            cpasync16(&Ws2[s*2560 + r*20 + qd], &W[(size_t)(col0+r)*DMODEL + k0 + qd]);
        }
        asm volatile("cp.async.commit_group;");
    };
    #pragma unroll
    for (int t = 0; t < VPSTG - 1; t++) prefetch(t);

    float acc[2][8][4] = {};
    for (int t = 0; t < ntiles; t++) {
        int s = t & (VPSTG - 1);
        asm volatile("cp.async.wait_group %0;" :: "n"(VPSTG - 2));
        __syncthreads();
        const float* Ap = &As2[s*2560];
        const float* Wp = &Ws2[s*2560];
        #pragma unroll
        for (int kk = 0; kk < 16; kk += 8) {
            const int kr = kk + (lane & 3), m0 = wm + (lane >> 2);
            unsigned af[2][4];
            #pragma unroll
            for (int i = 0; i < 2; i++) {
                af[i][0] = __float_as_uint(Ap[(m0+i*16)*20 + kr]);
                af[i][1] = __float_as_uint(Ap[(m0+i*16+8)*20 + kr]);
                af[i][2] = __float_as_uint(Ap[(m0+i*16)*20 + kr+4]);
                af[i][3] = __float_as_uint(Ap[(m0+i*16+8)*20 + kr+4]);
            }
            #pragma unroll
            for (int j = 0; j < 8; j++) {
                int nb = wn + j * 8 + (lane >> 2);
                unsigned bf[2] = {__float_as_uint(Wp[nb*20 + kr]),
                                  __float_as_uint(Wp[nb*20 + kr+4])};
                mma8(acc[0][j], af[0], bf);
                mma8(acc[1][j], af[1], bf);
            }
        }
        __syncthreads();
        if (t + VPSTG - 1 < ntiles) prefetch(t + VPSTG - 1);
        else asm volatile("cp.async.commit_group;");
    }
    #pragma unroll
    for (int j = 0; j < 8; j++) {
        int c = col0 + wn + j * 8 + (lane & 3) * 2;
        float2 bb = *(const float2*)&bias[c];
        #pragma unroll
        for (int i = 0; i < 2; i++) {
            size_t r = row0 + wm + i * 16 + (lane >> 2);
            float2 o0 = {acc[i][j][0] + bb.x, acc[i][j][1] + bb.y};
            float2 o1 = {acc[i][j][2] + bb.x, acc[i][j][3] + bb.y};
            *(float2*)&C[r * DMODEL + c]       = o0;
            *(float2*)&C[(r + 8) * DMODEL + c] = o1;
        }
    }
}

// ---------------------------------------------------------------------------
// O projection: A = pctx0 + pctx1 (summed at fragment load), cp.async
// 3-stage, 3 streams. block 128x128, BK=16.
// ---------------------------------------------------------------------------
__global__ __launch_bounds__(256, 2)
void gemm_o_tf32(const float* __restrict__ pctx, const float* __restrict__ W,
                 const float* __restrict__ bias, float* __restrict__ C) {
    extern __shared__ float osm[];
    float* As0 = osm;                  // [OPSTG][128][20]
    float* As1 = osm + OP_AS;          // [OPSTG][128][20]
    float* Ws2 = osm + 2 * OP_AS;      // [OPSTG][128][20]
    const int tid = threadIdx.x, lane = tid & 31, warp = tid >> 5;
    const int wm = (warp & 3) * 32, wn = (warp >> 2) * 64;
    const int row0 = blockIdx.y * 128, col0 = blockIdx.x * 128;
    const size_t PS = (size_t)MROWS * DMODEL;
    const int ntiles = DMODEL / 16;

    auto prefetch = [&](int t) {
        int s = t % OPSTG;
        int k0 = t * 16;
        #pragma unroll
        for (int l = 0; l < 2; l++) {
            int c = tid + l * 256, r = c >> 2, qd = (c & 3) * 4;
            size_t offA = (size_t)(row0 + r) * DMODEL + k0 + qd;
            cpasync16(&As0[s*2560 + r*20 + qd], &pctx[offA]);
            cpasync16(&As1[s*2560 + r*20 + qd], &pctx[offA + PS]);
            cpasync16(&Ws2[s*2560 + r*20 + qd], &W[(size_t)(col0+r)*DMODEL + k0 + qd]);
        }
        asm volatile("cp.async.commit_group;");
    };
    #pragma unroll
    for (int t = 0; t < OPSTG - 1; t++) prefetch(t);

    float acc[2][8][4] = {};
    for (int t = 0; t < ntiles; t++) {
        int s = t % OPSTG;
        asm volatile("cp.async.wait_group %0;" :: "n"(OPSTG - 2));
        __syncthreads();
        const float* A0 = &As0[s*2560];
        const float* A1 = &As1[s*2560];
        const float* Wp = &Ws2[s*2560];
        #pragma unroll
        for (int kk = 0; kk < 16; kk += 8) {
            const int kr = kk + (lane & 3), m0 = wm + (lane >> 2);
            unsigned af[2][4];
            #pragma unroll
            for (int i = 0; i < 2; i++) {
                int r0 = (m0 + i*16) * 20, r1 = (m0 + i*16 + 8) * 20;
                af[i][0] = __float_as_uint(A0[r0 + kr]   + A1[r0 + kr]);
                af[i][1] = __float_as_uint(A0[r1 + kr]   + A1[r1 + kr]);
                af[i][2] = __float_as_uint(A0[r0 + kr+4] + A1[r0 + kr+4]);
                af[i][3] = __float_as_uint(A0[r1 + kr+4] + A1[r1 + kr+4]);
            }
            #pragma unroll
            for (int j = 0; j < 8; j++) {
                int nb = wn + j * 8 + (lane >> 2);
                unsigned bf[2] = {__float_as_uint(Wp[nb*20 + kr]),
                                  __float_as_uint(Wp[nb*20 + kr+4])};
                mma8(acc[0][j], af[0], bf);
                mma8(acc[1][j], af[1], bf);
            }
        }
        __syncthreads();
        if (t + OPSTG - 1 < ntiles) prefetch(t + OPSTG - 1);
        else asm volatile("cp.async.commit_group;");
    }
    #pragma unroll
    for (int j = 0; j < 8; j++) {
        int c = col0 + wn + j * 8 + (lane & 3) * 2;
        float2 bb = *(const float2*)&bias[c];
        #pragma unroll
        for (int i = 0; i < 2; i++) {
            size_t r = row0 + wm + i * 16 + (lane >> 2);
            float2 o0 = {acc[i][j][0] + bb.x, acc[i][j][1] + bb.y};
            float2 o1 = {acc[i][j][2] + bb.x, acc[i][j][3] + bb.y};
            *(float2*)&C[r * DMODEL + c]       = o0;
            *(float2*)&C[(r + 8) * DMODEL + c] = o1;
        }
    }
}

// ---------------------------------------------------------------------------
// q+k projections, 3xBF16 split, register-pipelined, batched on blockIdx.z.
// ---------------------------------------------------------------------------
__global__ __launch_bounds__(256, 2)
void gemm_qk_bf16x3(const float* __restrict__ qin, const float* __restrict__ kin,
                    const float* __restrict__ wq, const float* __restrict__ wk,
                    const float* __restrict__ bq, const float* __restrict__ bk,
                    float* __restrict__ gq, float* __restrict__ gk) {
    const float* A    = blockIdx.z ? kin : qin;
    const float* W    = blockIdx.z ? wk  : wq;
    const float* bias = blockIdx.z ? bk  : bq;
    float* C          = blockIdx.z ? gk  : gq;

    __shared__ unsigned Ah2[2][8][132], Al2[2][8][132];
    __shared__ unsigned Bh2[2][8][132], Bl2[2][8][132];
    const int tid = threadIdx.x, lane = tid & 31, warp = tid >> 5;
    const int wm = (warp & 3) * 32, wn = (warp >> 2) * 64;
    const int row0 = blockIdx.y * 128, col0 = blockIdx.x * 128;
    const int kq = lane & 3;

    float4 ra[2], rb[2];
    auto doload = [&](int k0) {
        #pragma unroll
        for (int l = 0; l < 2; l++) {
            int idx = tid + l * 256, r = idx >> 2, kc = (idx & 3) << 2;
            ra[l] = *(const float4*)&A[(size_t)(row0 + r) * DMODEL + k0 + kc];
            rb[l] = *(const float4*)&W[(size_t)(col0 + r) * DMODEL + k0 + kc];
        }
    };
    auto dostore = [&](int bf) {
        #pragma unroll
        for (int l = 0; l < 2; l++) {
            int idx = tid + l * 256, r = idx >> 2, kc = (idx & 3) << 2, kp = kc >> 1;
            unsigned h0, l0, h1, l1;
            splitbf2(ra[l].x, ra[l].y, h0, l0); splitbf2(ra[l].z, ra[l].w, h1, l1);
            Ah2[bf][kp][r] = h0; Ah2[bf][kp+1][r] = h1;
            Al2[bf][kp][r] = l0; Al2[bf][kp+1][r] = l1;
            splitbf2(rb[l].x, rb[l].y, h0, l0); splitbf2(rb[l].z, rb[l].w, h1, l1);
            Bh2[bf][kp][r] = h0; Bh2[bf][kp+1][r] = h1;
            Bl2[bf][kp][r] = l0; Bl2[bf][kp+1][r] = l1;
        }
    };

    float acc[2][8][4] = {};
    doload(0); dostore(0); __syncthreads();
    int bf = 0;
    for (int k0 = 0; k0 < DMODEL; k0 += 16) {
        bool more = (k0 + 16 < DMODEL);
        if (more) doload(k0 + 16);
        unsigned ah[2][4], al[2][4];
        #pragma unroll
        for (int i = 0; i < 2; i++) {
            int m0 = wm + i * 16 + (lane >> 2);
            ah[i][0]=Ah2[bf][kq][m0];   ah[i][1]=Ah2[bf][kq][m0+8];
            ah[i][2]=Ah2[bf][kq+4][m0]; ah[i][3]=Ah2[bf][kq+4][m0+8];
            al[i][0]=Al2[bf][kq][m0];   al[i][1]=Al2[bf][kq][m0+8];
            al[i][2]=Al2[bf][kq+4][m0]; al[i][3]=Al2[bf][kq+4][m0+8];
        }
        #pragma unroll
        for (int j = 0; j < 8; j++) {
            int nb = wn + j * 8 + (lane >> 2);
            unsigned bh2[2] = {Bh2[bf][kq][nb], Bh2[bf][kq+4][nb]};
            unsigned bl2[2] = {Bl2[bf][kq][nb], Bl2[bf][kq+4][nb]};
            #pragma unroll
            for (int i = 0; i < 2; i++) {
                mma16(acc[i][j], al[i], bh2);
                mma16(acc[i][j], ah[i], bl2);
                mma16(acc[i][j], ah[i], bh2);
            }
        }
        if (more) { dostore(bf ^ 1); __syncthreads(); bf ^= 1; }
    }
    #pragma unroll
    for (int j = 0; j < 8; j++) {
        int c = col0 + wn + j * 8 + (lane & 3) * 2;
        float2 bb = *(const float2*)&bias[c];
        #pragma unroll
        for (int i = 0; i < 2; i++) {
            size_t r = row0 + wm + i * 16 + (lane >> 2);
            float2 o0 = {acc[i][j][0] + bb.x, acc[i][j][1] + bb.y};
            float2 o1 = {acc[i][j][2] + bb.x, acc[i][j][3] + bb.y};
            *(float2*)&C[r * DMODEL + c]       = o0;
            *(float2*)&C[(r + 8) * DMODEL + c] = o1;
        }
    }
}

// ---------------------------------------------------------------------------
// Fused scores (3xBF16) + mask + exp -> unnormalized P + rowsum partials.
// grid (32 bh, NKT ktile, 16 qtile): bh fastest for mask L2 reuse.
// P written with streaming hint (evicted before pv anyway; protect L2).
// ---------------------------------------------------------------------------
__global__ __launch_bounds__(256, 2)
void scores_exp(const float* __restrict__ gq, const float* __restrict__ gk,
                const int* __restrict__ mask, float* __restrict__ attn,
                float* __restrict__ partial) {
    extern __shared__ unsigned dsm[];
    unsigned (*Ah2)[132] = (unsigned(*)[132])dsm;        // [32][132]
    unsigned (*Al2)[132] = Ah2 + 32;
    unsigned (*Bh2)[132] = Al2 + 32;
    unsigned (*Bl2)[132] = Bh2 + 32;
    float* sums = (float*)(Bl2 + 32);                    // [2][128]

    const int tid = threadIdx.x, lane = tid & 31, warp = tid >> 5;
    const int wm = (warp & 3) * 32, wn = (warp >> 2) * 64;
    const int bh_i = blockIdx.x, b = bh_i >> 4, h = bh_i & 15;
    const int ktile = blockIdx.y;
    const int c0 = ktile * 128, q0 = blockIdx.z * 128;
    const float* Qb = gq + (size_t)b * SEQ * DMODEL + h * DHEAD;
    const float* Kb = gk + (size_t)b * SEQ * DMODEL + h * DHEAD;
    const int kq = lane & 3;

    #pragma unroll
    for (int l = 0; l < 8; l++) {
        int idx = tid + l * 256, r = idx >> 4, kc = (idx & 15) << 2, kp = kc >> 1;
        float4 a4 = *(const float4*)&Qb[(size_t)(q0 + r) * DMODEL + kc];
        float4 b4 = *(const float4*)&Kb[(size_t)(c0 + r) * DMODEL + kc];
        unsigned h0, l0, h1, l1;
        splitbf2(a4.x, a4.y, h0, l0); splitbf2(a4.z, a4.w, h1, l1);
        Ah2[kp][r] = h0; Ah2[kp+1][r] = h1; Al2[kp][r] = l0; Al2[kp+1][r] = l1;
        splitbf2(b4.x, b4.y, h0, l0); splitbf2(b4.z, b4.w, h1, l1);
        Bh2[kp][r] = h0; Bh2[kp+1][r] = h1; Bl2[kp][r] = l0; Bl2[kp+1][r] = l1;
    }
    __syncthreads();

    float acc[2][8][4] = {};
    #pragma unroll
    for (int kk = 0; kk < 32; kk += 8) {
        unsigned ah[2][4], al[2][4];
        #pragma unroll
        for (int i = 0; i < 2; i++) {
            int m0 = wm + i * 16 + (lane >> 2);
            ah[i][0]=Ah2[kk+kq][m0];   ah[i][1]=Ah2[kk+kq][m0+8];
            ah[i][2]=Ah2[kk+kq+4][m0]; ah[i][3]=Ah2[kk+kq+4][m0+8];
            al[i][0]=Al2[kk+kq][m0];   al[i][1]=Al2[kk+kq][m0+8];
            al[i][2]=Al2[kk+kq+4][m0]; al[i][3]=Al2[kk+kq+4][m0+8];
        }
        #pragma unroll
        for (int j = 0; j < 8; j++) {
            int nb = wn + j * 8 + (lane >> 2);
            unsigned bh2[2] = {Bh2[kk+kq][nb], Bh2[kk+kq+4][nb]};
            unsigned bl2[2] = {Bl2[kk+kq][nb], Bl2[kk+kq+4][nb]};
            #pragma unroll
            for (int i = 0; i < 2; i++) {
                mma16(acc[i][j], al[i], bh2);
                mma16(acc[i][j], ah[i], bl2);
                mma16(acc[i][j], ah[i], bh2);
            }
        }
    }

    const int* mrow = mask + (size_t)b * SEQ * SEQ;
    float* out = attn + (size_t)bh_i * SEQ * SEQ;
    float rs[2][2] = {};
    #pragma unroll
    for (int j = 0; j < 8; j++) {
        int c = c0 + wn + j * 8 + (lane & 3) * 2;
        #pragma unroll
        for (int i = 0; i < 2; i++) {
            size_t r = q0 + wm + i * 16 + (lane >> 2);
            int2 m0v = *(const int2*)&mrow[r * SEQ + c];
            int2 m1v = *(const int2*)&mrow[(r + 8) * SEQ + c];
            float2 o0, o1;
            o0.x = m0v.x ? __expf(acc[i][j][0] * 0.125f) : 0.f;
            o0.y = m0v.y ? __expf(acc[i][j][1] * 0.125f) : 0.f;
            o1.x = m1v.x ? __expf(acc[i][j][2] * 0.125f) : 0.f;
            o1.y = m1v.y ? __expf(acc[i][j][3] * 0.125f) : 0.f;
            __stcs((float2*)&out[r * SEQ + c],       o0);
            __stcs((float2*)&out[(r + 8) * SEQ + c], o1);
            rs[i][0] += o0.x + o0.y;
            rs[i][1] += o1.x + o1.y;
        }
    }
    #pragma unroll
    for (int i = 0; i < 2; i++)
        #pragma unroll
        for (int hh = 0; hh < 2; hh++) {
            float v = rs[i][hh];
            v += __shfl_xor_sync(0xffffffffu, v, 1);
            v += __shfl_xor_sync(0xffffffffu, v, 2);
            if ((lane & 3) == 0)
                sums[(warp >> 2) * 128 + wm + i * 16 + hh * 8 + (lane >> 2)] = v;
        }
    __syncthreads();
    if (tid < 128) {
        float tot = sums[tid] + sums[128 + tid];
        partial[((size_t)bh_i * SEQ + q0 + tid) * NKT + ktile] = tot;
    }
}

// ---------------------------------------------------------------------------
// Fused PV (tf32, split-K=2) with cp.async 3-stage pipeline, 4 CTAs/SM.
// MMA consumes UNNORMALIZED P; accumulators scaled by inv rowsum at epilogue.
// Normalized P written (streaming hint) from the smem tiles.
// grid (SPLITK, 16, 32).
// ---------------------------------------------------------------------------
__global__ __launch_bounds__(256, 4)
void pv_norm(float* __restrict__ attn, const float* __restrict__ gv,
             const float* __restrict__ partial, float* __restrict__ pctx) {
    extern __shared__ float psm[];
    float* Ps    = psm;                    // [PVSTG][128][20]
    float* Vs    = psm + PV_PS;            // [PVSTG][16][72]
    float* inv_s = psm + PV_PS + PV_VS;    // [128]

    const int tid = threadIdx.x, lane = tid & 31, warp = tid >> 5;
    const int wm = (warp & 3) * 32, wn = (warp >> 2) * 32;
    const int bh_i = blockIdx.z, b = bh_i >> 4, h = bh_i & 15;
    float* P = attn + (size_t)bh_i * SEQ * SEQ;
    const float* V = gv + (size_t)b * SEQ * DMODEL + h * DHEAD;
    float* Cc = pctx + (size_t)blockIdx.x * MROWS * DMODEL
                     + (size_t)b * SEQ * DMODEL + h * DHEAD;
    const int q0 = blockIdx.y * 128;
    const int kbase = blockIdx.x * (SEQ / SPLITK);
    const int ntiles = (SEQ / SPLITK) / 16;     // 64

    auto prefetch = [&](int t) {
        int s = t % PVSTG;
        int k0 = kbase + t * 16;
        #pragma unroll
        for (int l = 0; l < 2; l++) {
            int c = tid + l * 256, r = c >> 2, qd = (c & 3) * 4;
            cpasync16(&Ps[s*2560 + r*20 + qd], &P[(size_t)(q0+r)*SEQ + k0 + qd]);
        }
        {
            int kk = tid >> 4, n = (tid & 15) * 4;
            cpasync16(&Vs[s*1152 + kk*72 + n], &V[(size_t)(k0+kk)*DMODEL + n]);
        }
        asm volatile("cp.async.commit_group;");
    };
    #pragma unroll
    for (int t = 0; t < PVSTG - 1; t++) prefetch(t);

    if (tid < 128) {
        const float4* pp = (const float4*)&partial[((size_t)bh_i * SEQ + q0 + tid) * NKT];
        float4 p0 = pp[0], p1 = pp[1], p2 = pp[2], p3 = pp[3];
        float s = ((p0.x + p0.y) + (p0.z + p0.w)) + ((p1.x + p1.y) + (p1.z + p1.w))
                + ((p2.x + p2.y) + (p2.z + p2.w)) + ((p3.x + p3.y) + (p3.z + p3.w));
        inv_s[tid] = 1.0f / s;
    }

    float acc[2][4][4] = {};
    for (int t = 0; t < ntiles; t++) {
        int s = t % PVSTG;
        asm volatile("cp.async.wait_group %0;" :: "n"(PVSTG - 2));
        __syncthreads();
        const float* Pp = &Ps[s*2560];
        const float* Vp = &Vs[s*1152];
        #pragma unroll
        for (int kk = 0; kk < 16; kk += 8) {
            const int kr = kk + (lane & 3), m0 = wm + (lane >> 2);
            unsigned af[2][4];
            #pragma unroll
            for (int i = 0; i < 2; i++) {
                af[i][0] = __float_as_uint(Pp[(m0+i*16)*20 + kr]);
                af[i][1] = __float_as_uint(Pp[(m0+i*16+8)*20 + kr]);
                af[i][2] = __float_as_uint(Pp[(m0+i*16)*20 + kr+4]);
                af[i][3] = __float_as_uint(Pp[(m0+i*16+8)*20 + kr+4]);
            }
            #pragma unroll
            for (int j = 0; j < 4; j++) {
                int nb = wn + j * 8 + (lane >> 2);
                unsigned bfr[2] = {__float_as_uint(Vp[kr*72 + nb]),
                                   __float_as_uint(Vp[(kr+4)*72 + nb])};
                mma8(acc[0][j], af[0], bfr);
                mma8(acc[1][j], af[1], bfr);
            }
        }
        // write normalized attention from the smem tile (streaming)
        {
            int k0 = kbase + t * 16;
            #pragma unroll
            for (int l = 0; l < 2; l++) {
                int c = tid + l * 256, r = c >> 2, qd = (c & 3) * 4;
                float4 a4 = *(const float4*)&Pp[r*20 + qd];
                float sc = inv_s[r];
                a4.x *= sc; a4.y *= sc; a4.z *= sc; a4.w *= sc;
                __stcs((float4*)&P[(size_t)(q0+r)*SEQ + k0 + qd], a4);
            }
        }
        __syncthreads();
        if (t + PVSTG - 1 < ntiles) prefetch(t + PVSTG - 1);
        else asm volatile("cp.async.commit_group;");
    }
    #pragma unroll
    for (int j = 0; j < 4; j++) {
        int c = wn + j * 8 + (lane & 3) * 2;
        #pragma unroll
        for (int i = 0; i < 2; i++) {
            int rl = wm + i * 16 + (lane >> 2);
            float sc0 = inv_s[rl], sc1 = inv_s[rl + 8];
            size_t r = q0 + rl;
            float2 o0 = {acc[i][j][0] * sc0, acc[i][j][1] * sc0};
            float2 o1 = {acc[i][j][2] * sc1, acc[i][j][3] * sc1};
            *(float2*)&Cc[r * DMODEL + c]       = o0;
            *(float2*)&Cc[(r + 8) * DMODEL + c] = o1;
        }
    }
}

// ---------------------------------------------------------------------------
// Residual + LayerNorm.
// ---------------------------------------------------------------------------
__global__ void ln_kernel(const float* __restrict__ resid,
                          const float* __restrict__ x,
                          const float* __restrict__ gamma,
                          const float* __restrict__ beta,
                          float* __restrict__ out) {
    const size_t row = blockIdx.x;
    const float4* xr = reinterpret_cast<const float4*>(x + row * DMODEL);
    const float4* rr = reinterpret_cast<const float4*>(resid + row * DMODEL);
    const int t = threadIdx.x;
    __shared__ float sred[8];

    float4 a = rr[t], bv = xr[t];
    float4 v = {a.x + bv.x, a.y + bv.y, a.z + bv.z, a.w + bv.w};
    float s = v.x + v.y + v.z + v.w;
    #pragma unroll
    for (int o = 16; o > 0; o >>= 1) s += __shfl_xor_sync(0xffffffffu, s, o);
    if ((t & 31) == 0) sred[t >> 5] = s;
    __syncthreads();
    float tot = 0.f;
    #pragma unroll
    for (int i = 0; i < 8; i++) tot += sred[i];
    const float mu = tot * (1.0f / DMODEL);
    __syncthreads();

    float dx = v.x - mu, dy = v.y - mu, dz = v.z - mu, dw = v.w - mu;
    float sq = dx*dx + dy*dy + dz*dz + dw*dw;
    #pragma unroll
    for (int o = 16; o > 0; o >>= 1) sq += __shfl_xor_sync(0xffffffffu, sq, o);
    if ((t & 31) == 0) sred[t >> 5] = sq;
    __syncthreads();
    float tot2 = 0.f;
    #pragma unroll
    for (int i = 0; i < 8; i++) tot2 += sred[i];
    const float inv = rsqrtf(tot2 * (1.0f / DMODEL) + 1e-5f);

    float4 g = reinterpret_cast<const float4*>(gamma)[t];
    float4 be = reinterpret_cast<const float4*>(beta)[t];
    float4 o;
    o.x = dx * inv * g.x + be.x;
    o.y = dy * inv * g.y + be.y;
    o.z = dz * inv * g.z + be.z;
    o.w = dw * inv * g.w + be.w;
    reinterpret_cast<float4*>(out + row * DMODEL)[t] = o;
}

// ---------------------------------------------------------------------------
extern "C" void kernel_launch(void* const* d_in, const int* in_sizes, int n_in,
                              void* d_out, int out_size) {
    const float* q     = (const float*)d_in[0];
    const float* k     = (const float*)d_in[1];
    const float* v     = (const float*)d_in[2];
    const int*   mask  = (const int*)  d_in[3];
    const float* wq    = (const float*)d_in[4];
    const float* bq    = (const float*)d_in[5];
    const float* wk    = (const float*)d_in[6];
    const float* bk    = (const float*)d_in[7];
    const float* wv    = (const float*)d_in[8];
    const float* bv    = (const float*)d_in[9];
    const float* wo    = (const float*)d_in[10];
    const float* bo    = (const float*)d_in[11];
    const float* gamma = (const float*)d_in[12];
    const float* beta  = (const float*)d_in[13];

    float* out  = (float*)d_out;
    float* attn = out + ATT_OFF;

    void* sp = nullptr;
    cudaGetSymbolAddress(&sp, g_scratch);
    const size_t PS = (size_t)MROWS * DMODEL;
    float* gq      = (float*)sp;
    float* gk      = gq + PS;
    float* gv      = gk + PS;
    float* go      = gv + PS;
    float* pctx    = go + PS;            // SPLITK x PS
    float* partial = pctx + SPLITK * PS;

    cudaFuncSetAttribute(scores_exp,   cudaFuncAttributeMaxDynamicSharedMemorySize, SC_SMEM);
    cudaFuncSetAttribute(pv_norm,      cudaFuncAttributeMaxDynamicSharedMemorySize, PV_SMEM);
    cudaFuncSetAttribute(gemm_nt_tf32, cudaFuncAttributeMaxDynamicSharedMemorySize, VP_SMEM);
    cudaFuncSetAttribute(gemm_o_tf32,  cudaFuncAttributeMaxDynamicSharedMemorySize, OP_SMEM);

    dim3 gQK(DMODEL / 128, MROWS / 128, 2);             // (8, 32, 2)
    gemm_qk_bf16x3<<<gQK, 256>>>(q, k, wq, wk, bq, bk, gq, gk);

    dim3 gProj(DMODEL / 128, MROWS / 128);              // (8, 32)
    gemm_nt_tf32<<<gProj, 256, VP_SMEM>>>(v, wv, bv, gv);

    dim3 gScores(BATCH * NHEADS, NKT, SEQ / 128);       // (32, 16, 16) bh fastest
    scores_exp<<<gScores, 256, SC_SMEM>>>(gq, gk, mask, attn, partial);

    dim3 gPV(SPLITK, SEQ / 128, BATCH * NHEADS);        // (2, 16, 32)
    pv_norm<<<gPV, 256, PV_SMEM>>>(attn, gv, partial, pctx);

    gemm_o_tf32<<<gProj, 256, OP_SMEM>>>(pctx, wo, bo, go);

    ln_kernel<<<MROWS, 256>>>(q, go, gamma, beta, out);
}

// round 11
// speedup vs baseline: 1.1165x; 1.0240x over previous
#include <cuda_runtime.h>
#include <cuda_bf16.h>
#include <math.h>

#define BATCH 2
#define SEQ   2048
#define DMODEL 1024
#define NHEADS 16
#define DHEAD  64
#define MROWS (BATCH*SEQ)                    // 4096
#define ATT_OFF ((size_t)BATCH*SEQ*DMODEL)
#define NKT 16
#define SPLITK 2
#define PVSTG 3
#define VPSTG 4
#define OPSTG 3
#define QKSTG 4

#define PS   ((size_t)MROWS * DMODEL)        // 4M floats
#define PKA  ((size_t)MROWS * 512)           // 2M u32 (kpairs per 4096x1024 matrix)
#define PKW  ((size_t)DMODEL * 512)          // 0.5M u32
#define PARTIAL_SZ ((size_t)BATCH * NHEADS * SEQ * NKT)

// gv, go, pctx(2), partial, input packs (8*PKA? -> 4*PKA + 4*PKW), output packs 4*PKA
__device__ float g_scratch[4ull * PS + PARTIAL_SZ + 8ull * PKA + 4ull * PKW];

// scores smem: Qh/Ql/Kh/Kl [128][36] u32 + sums[2][128]
#define SC_SMEM (4 * 128 * 36 * 4 + 256 * 4)
// pv smem
#define PV_PS   (PVSTG * 128 * 20)
#define PV_VS   (PVSTG * 16 * 72)
#define PV_SMEM ((PV_PS + PV_VS + 128) * 4)
// vproj smem
#define VP_AS   (VPSTG * 128 * 20)
#define VP_SMEM (2 * VP_AS * 4)
// oproj smem
#define OP_AS   (OPSTG * 128 * 20)
#define OP_SMEM (3 * OP_AS * 4)
// qk smem: 4 arrays x QKSTG stages x [128][12]
#define QK_ARR  (QKSTG * 128 * 12)
#define QK_SMEM (4 * QK_ARR * 4)

// ---------------------------------------------------------------------------
__device__ __forceinline__ void mma8(float* d, const unsigned* a, const unsigned* b) {
    asm volatile(
        "mma.sync.aligned.m16n8k8.row.col.f32.tf32.tf32.f32 "
        "{%0,%1,%2,%3}, {%4,%5,%6,%7}, {%8,%9}, {%0,%1,%2,%3};"
        : "+f"(d[0]), "+f"(d[1]), "+f"(d[2]), "+f"(d[3])
        : "r"(a[0]), "r"(a[1]), "r"(a[2]), "r"(a[3]), "r"(b[0]), "r"(b[1]));
}
__device__ __forceinline__ void mma16(float* d, const unsigned* a, const unsigned* b) {
    asm volatile(
        "mma.sync.aligned.m16n8k16.row.col.f32.bf16.bf16.f32 "
        "{%0,%1,%2,%3}, {%4,%5,%6,%7}, {%8,%9}, {%0,%1,%2,%3};"
        : "+f"(d[0]), "+f"(d[1]), "+f"(d[2]), "+f"(d[3])
        : "r"(a[0]), "r"(a[1]), "r"(a[2]), "r"(a[3]), "r"(b[0]), "r"(b[1]));
}
__device__ __forceinline__ void splitbf2(float x, float y, unsigned& hi, unsigned& lo) {
    __nv_bfloat16 hx = __float2bfloat16_rn(x);
    __nv_bfloat16 hy = __float2bfloat16_rn(y);
    __nv_bfloat16 lx = __float2bfloat16_rn(x - __bfloat162float(hx));
    __nv_bfloat16 ly = __float2bfloat16_rn(y - __bfloat162float(hy));
    hi = (unsigned)__bfloat16_as_ushort(hx) | ((unsigned)__bfloat16_as_ushort(hy) << 16);
    lo = (unsigned)__bfloat16_as_ushort(lx) | ((unsigned)__bfloat16_as_ushort(ly) << 16);
}
__device__ __forceinline__ void cpasync16(void* sm, const void* gm) {
    unsigned a = (unsigned)__cvta_generic_to_shared(sm);
    asm volatile("cp.async.cg.shared.global [%0], [%1], 16;" :: "r"(a), "l"(gm));
}

// ---------------------------------------------------------------------------
// Prepack: fp32 -> packed bf16 (hi,lo) kpair arrays. Each thread: 2 kpairs.
// ---------------------------------------------------------------------------
__global__ void prepack(const float* __restrict__ src, unsigned* __restrict__ hi,
                        unsigned* __restrict__ lo, int npairs) {
    int i = blockIdx.x * 256 + threadIdx.x;
    if (i < npairs / 2) {
        float4 v = ((const float4*)src)[i];
        unsigned h0, l0, h1, l1;
        splitbf2(v.x, v.y, h0, l0);
        splitbf2(v.z, v.w, h1, l1);
        ((uint2*)hi)[i] = make_uint2(h0, h1);
        ((uint2*)lo)[i] = make_uint2(l0, l1);
    }
}

// ---------------------------------------------------------------------------
// q+k projections from PREPACKED operands, 3xBF16, cp.async 4-stage.
// Epilogue emits prepacked (hi,lo) outputs for scores. z=0: q, z=1: k.
// ---------------------------------------------------------------------------
__global__ __launch_bounds__(256, 2)
void gemm_qk_pk(const unsigned* __restrict__ apk, const unsigned* __restrict__ wpk,
                const float* __restrict__ bq, const float* __restrict__ bk,
                unsigned* __restrict__ outpk) {
    extern __shared__ unsigned qsm[];
    unsigned* Ah = qsm;                 // [QKSTG][128][12]
    unsigned* Al = qsm + QK_ARR;
    unsigned* Wh = qsm + 2 * QK_ARR;
    unsigned* Wl = qsm + 3 * QK_ARR;
    const int z = blockIdx.z;
    const unsigned* Ahi = apk + (size_t)z * 2 * PKA;
    const unsigned* Alo = Ahi + PKA;
    const unsigned* Whi = wpk + (size_t)z * 2 * PKW;
    const unsigned* Wlo = Whi + PKW;
    unsigned* Ohi = outpk + (size_t)z * 2 * PKA;
    unsigned* Olo = Ohi + PKA;
    const float* bias = z ? bk : bq;

    const int tid = threadIdx.x, lane = tid & 31, warp = tid >> 5;
    const int wm = (warp & 3) * 32, wn = (warp >> 2) * 64, kq = lane & 3;
    const int row0 = blockIdx.y * 128, col0 = blockIdx.x * 128;
    const int ntiles = 512 / 8;   // 64 stages of 8 kpairs (16 k-elems)

    const int pr = tid >> 1, pk4 = (tid & 1) * 4;
    auto prefetch = [&](int t) {
        int s = t & (QKSTG - 1);
        int kp0 = t * 8;
        cpasync16(&Ah[s*1536 + pr*12 + pk4], &Ahi[(size_t)(row0+pr)*512 + kp0 + pk4]);
        cpasync16(&Al[s*1536 + pr*12 + pk4], &Alo[(size_t)(row0+pr)*512 + kp0 + pk4]);
        cpasync16(&Wh[s*1536 + pr*12 + pk4], &Whi[(size_t)(col0+pr)*512 + kp0 + pk4]);
        cpasync16(&Wl[s*1536 + pr*12 + pk4], &Wlo[(size_t)(col0+pr)*512 + kp0 + pk4]);
        asm volatile("cp.async.commit_group;");
    };
    #pragma unroll
    for (int t = 0; t < QKSTG - 1; t++) prefetch(t);

    float acc[2][8][4] = {};
    for (int t = 0; t < ntiles; t++) {
        int s = t & (QKSTG - 1);
        asm volatile("cp.async.wait_group %0;" :: "n"(QKSTG - 2));
        __syncthreads();
        const unsigned* Ahp = &Ah[s*1536];
        const unsigned* Alp = &Al[s*1536];
        const unsigned* Whp = &Wh[s*1536];
        const unsigned* Wlp = &Wl[s*1536];
        unsigned ah[2][4], al[2][4];
        #pragma unroll
        for (int i = 0; i < 2; i++) {
            int m0 = wm + i * 16 + (lane >> 2);
            ah[i][0] = Ahp[m0*12 + kq];     ah[i][1] = Ahp[(m0+8)*12 + kq];
            ah[i][2] = Ahp[m0*12 + kq+4];   ah[i][3] = Ahp[(m0+8)*12 + kq+4];
            al[i][0] = Alp[m0*12 + kq];     al[i][1] = Alp[(m0+8)*12 + kq];
            al[i][2] = Alp[m0*12 + kq+4];   al[i][3] = Alp[(m0+8)*12 + kq+4];
        }
        #pragma unroll
        for (int j = 0; j < 8; j++) {
            int nb = wn + j * 8 + (lane >> 2);
            unsigned bh2[2] = {Whp[nb*12 + kq], Whp[nb*12 + kq+4]};
            unsigned bl2[2] = {Wlp[nb*12 + kq], Wlp[nb*12 + kq+4]};
            #pragma unroll
            for (int i = 0; i < 2; i++) {
                mma16(acc[i][j], al[i], bh2);
                mma16(acc[i][j], ah[i], bl2);
                mma16(acc[i][j], ah[i], bh2);
            }
        }
        __syncthreads();
        if (t + QKSTG - 1 < ntiles) prefetch(t + QKSTG - 1);
        else asm volatile("cp.async.commit_group;");
    }
    #pragma unroll
    for (int j = 0; j < 8; j++) {
        int c = col0 + wn + j * 8 + (lane & 3) * 2;
        float2 bb = *(const float2*)&bias[c];
        #pragma unroll
        for (int i = 0; i < 2; i++) {
            size_t r = row0 + wm + i * 16 + (lane >> 2);
            unsigned h, l;
            splitbf2(acc[i][j][0] + bb.x, acc[i][j][1] + bb.y, h, l);
            Ohi[r * 512 + (c >> 1)] = h;  Olo[r * 512 + (c >> 1)] = l;
            splitbf2(acc[i][j][2] + bb.x, acc[i][j][3] + bb.y, h, l);
            Ohi[(r + 8) * 512 + (c >> 1)] = h;  Olo[(r + 8) * 512 + (c >> 1)] = l;
        }
    }
}

// ---------------------------------------------------------------------------
// V projection (1xTF32), cp.async 4-stage, raw fp32 smem tiles.
// ---------------------------------------------------------------------------
__global__ __launch_bounds__(256, 2)
void gemm_nt_tf32(const float* __restrict__ A, const float* __restrict__ W,
                  const float* __restrict__ bias, float* __restrict__ C) {
    extern __shared__ float vsm[];
    float* As2 = vsm;
    float* Ws2 = vsm + VP_AS;
    const int tid = threadIdx.x, lane = tid & 31, warp = tid >> 5;
    const int wm = (warp & 3) * 32, wn = (warp >> 2) * 64;
    const int row0 = blockIdx.y * 128, col0 = blockIdx.x * 128;
    const int ntiles = DMODEL / 16;

    auto prefetch = [&](int t) {
        int s = t & (VPSTG - 1);
        int k0 = t * 16;
        #pragma unroll
        for (int l = 0; l < 2; l++) {
            int c = tid + l * 256, r = c >> 2, qd = (c & 3) * 4;
            cpasync16(&As2[s*2560 + r*20 + qd], &A[(size_t)(row0+r)*DMODEL + k0 + qd]);
            cpasync16(&Ws2[s*2560 + r*20 + qd], &W[(size_t)(col0+r)*DMODEL + k0 + qd]);
        }
        asm volatile("cp.async.commit_group;");
    };
    #pragma unroll
    for (int t = 0; t < VPSTG - 1; t++) prefetch(t);

    float acc[2][8][4] = {};
    for (int t = 0; t < ntiles; t++) {
        int s = t & (VPSTG - 1);
        asm volatile("cp.async.wait_group %0;" :: "n"(VPSTG - 2));
        __syncthreads();
        const float* Ap = &As2[s*2560];
        const float* Wp = &Ws2[s*2560];
        #pragma unroll
        for (int kk = 0; kk < 16; kk += 8) {
            const int kr = kk + (lane & 3), m0 = wm + (lane >> 2);
            unsigned af[2][4];
            #pragma unroll
            for (int i = 0; i < 2; i++) {
                af[i][0] = __float_as_uint(Ap[(m0+i*16)*20 + kr]);
                af[i][1] = __float_as_uint(Ap[(m0+i*16+8)*20 + kr]);
                af[i][2] = __float_as_uint(Ap[(m0+i*16)*20 + kr+4]);
                af[i][3] = __float_as_uint(Ap[(m0+i*16+8)*20 + kr+4]);
            }
            #pragma unroll
            for (int j = 0; j < 8; j++) {
                int nb = wn + j * 8 + (lane >> 2);
                unsigned bf[2] = {__float_as_uint(Wp[nb*20 + kr]),
                                  __float_as_uint(Wp[nb*20 + kr+4])};
                mma8(acc[0][j], af[0], bf);
                mma8(acc[1][j], af[1], bf);
            }
        }
        __syncthreads();
        if (t + VPSTG - 1 < ntiles) prefetch(t + VPSTG - 1);
        else asm volatile("cp.async.commit_group;");
    }
    #pragma unroll
    for (int j = 0; j < 8; j++) {
        int c = col0 + wn + j * 8 + (lane & 3) * 2;
        float2 bb = *(const float2*)&bias[c];
        #pragma unroll
        for (int i = 0; i < 2; i++) {
            size_t r = row0 + wm + i * 16 + (lane >> 2);
            float2 o0 = {acc[i][j][0] + bb.x, acc[i][j][1] + bb.y};
            float2 o1 = {acc[i][j][2] + bb.x, acc[i][j][3] + bb.y};
            *(float2*)&C[r * DMODEL + c]       = o0;
            *(float2*)&C[(r + 8) * DMODEL + c] = o1;
        }
    }
}

// ---------------------------------------------------------------------------
// O projection: A = pctx0 + pctx1, cp.async 3-stage, 3 streams.
// ---------------------------------------------------------------------------
__global__ __launch_bounds__(256, 2)
void gemm_o_tf32(const float* __restrict__ pctx, const float* __restrict__ W,
                 const float* __restrict__ bias, float* __restrict__ C) {
    extern __shared__ float osm[];
    float* As0 = osm;
    float* As1 = osm + OP_AS;
    float* Ws2 = osm + 2 * OP_AS;
    const int tid = threadIdx.x, lane = tid & 31, warp = tid >> 5;
    const int wm = (warp & 3) * 32, wn = (warp >> 2) * 64;
    const int row0 = blockIdx.y * 128, col0 = blockIdx.x * 128;
    const int ntiles = DMODEL / 16;

    auto prefetch = [&](int t) {
        int s = t % OPSTG;
        int k0 = t * 16;
        #pragma unroll
        for (int l = 0; l < 2; l++) {
            int c = tid + l * 256, r = c >> 2, qd = (c & 3) * 4;
            size_t offA = (size_t)(row0 + r) * DMODEL + k0 + qd;
            cpasync16(&As0[s*2560 + r*20 + qd], &pctx[offA]);
            cpasync16(&As1[s*2560 + r*20 + qd], &pctx[offA + PS]);
            cpasync16(&Ws2[s*2560 + r*20 + qd], &W[(size_t)(col0+r)*DMODEL + k0 + qd]);
        }
        asm volatile("cp.async.commit_group;");
    };
    #pragma unroll
    for (int t = 0; t < OPSTG - 1; t++) prefetch(t);

    float acc[2][8][4] = {};
    for (int t = 0; t < ntiles; t++) {
        int s = t % OPSTG;
        asm volatile("cp.async.wait_group %0;" :: "n"(OPSTG - 2));
        __syncthreads();
        const float* A0 = &As0[s*2560];
        const float* A1 = &As1[s*2560];
        const float* Wp = &Ws2[s*2560];
        #pragma unroll
        for (int kk = 0; kk < 16; kk += 8) {
            const int kr = kk + (lane & 3), m0 = wm + (lane >> 2);
            unsigned af[2][4];
            #pragma unroll
            for (int i = 0; i < 2; i++) {
                int r0 = (m0 + i*16) * 20, r1 = (m0 + i*16 + 8) * 20;
                af[i][0] = __float_as_uint(A0[r0 + kr]   + A1[r0 + kr]);
                af[i][1] = __float_as_uint(A0[r1 + kr]   + A1[r1 + kr]);
                af[i][2] = __float_as_uint(A0[r0 + kr+4] + A1[r0 + kr+4]);
                af[i][3] = __float_as_uint(A0[r1 + kr+4] + A1[r1 + kr+4]);
            }
            #pragma unroll
            for (int j = 0; j < 8; j++) {
                int nb = wn + j * 8 + (lane >> 2);
                unsigned bf[2] = {__float_as_uint(Wp[nb*20 + kr]),
                                  __float_as_uint(Wp[nb*20 + kr+4])};
                mma8(acc[0][j], af[0], bf);
                mma8(acc[1][j], af[1], bf);
            }
        }
        __syncthreads();
        if (t + OPSTG - 1 < ntiles) prefetch(t + OPSTG - 1);
        else asm volatile("cp.async.commit_group;");
    }
    #pragma unroll
    for (int j = 0; j < 8; j++) {
        int c = col0 + wn + j * 8 + (lane & 3) * 2;
        float2 bb = *(const float2*)&bias[c];
        #pragma unroll
        for (int i = 0; i < 2; i++) {
            size_t r = row0 + wm + i * 16 + (lane >> 2);
            float2 o0 = {acc[i][j][0] + bb.x, acc[i][j][1] + bb.y};
            float2 o1 = {acc[i][j][2] + bb.x, acc[i][j][3] + bb.y};
            *(float2*)&C[r * DMODEL + c]       = o0;
            *(float2*)&C[(r + 8) * DMODEL + c] = o1;
        }
    }
}

// ---------------------------------------------------------------------------
// Fused scores (3xBF16) from PREPACKED gq/gk + mask + exp -> unnorm P + rowsums.
// cp.async one-shot strip load. grid (32 bh, NKT ktile, 16 qtile), bh fastest.
// ---------------------------------------------------------------------------
__global__ __launch_bounds__(256, 2)
void scores_exp(const unsigned* __restrict__ opk, const int* __restrict__ mask,
                float* __restrict__ attn, float* __restrict__ partial) {
    extern __shared__ unsigned dsm[];
    unsigned* Qh = dsm;                    // [128][36]
    unsigned* Ql = Qh + 128*36;
    unsigned* Kh = Ql + 128*36;
    unsigned* Kl = Kh + 128*36;
    float* sums = (float*)(Kl + 128*36);   // [2][128]

    const int tid = threadIdx.x, lane = tid & 31, warp = tid >> 5;
    const int wm = (warp & 3) * 32, wn = (warp >> 2) * 64, kq = lane & 3;
    const int bh_i = blockIdx.x, b = bh_i >> 4, h = bh_i & 15;
    const int c0 = blockIdx.y * 128, q0 = blockIdx.z * 128;
    const unsigned* Qhi = opk;
    const unsigned* Qlo = opk + PKA;
    const unsigned* Khi = opk + 2 * PKA;
    const unsigned* Klo = opk + 3 * PKA;
    const int hoff = h * 32;

    #pragma unroll
    for (int l = 0; l < 4; l++) {
        int idx = tid + l * 256, r = idx >> 3, kp4 = (idx & 7) * 4;
        size_t qoff = (size_t)(b * SEQ + q0 + r) * 512 + hoff + kp4;
        size_t koff = (size_t)(b * SEQ + c0 + r) * 512 + hoff + kp4;
        cpasync16(&Qh[r*36 + kp4], &Qhi[qoff]);
        cpasync16(&Ql[r*36 + kp4], &Qlo[qoff]);
        cpasync16(&Kh[r*36 + kp4], &Khi[koff]);
        cpasync16(&Kl[r*36 + kp4], &Klo[koff]);
    }
    asm volatile("cp.async.commit_group;");
    asm volatile("cp.async.wait_group 0;");
    __syncthreads();

    float acc[2][8][4] = {};
    #pragma unroll
    for (int kk = 0; kk < 32; kk += 8) {
        unsigned ah[2][4], al[2][4];
        #pragma unroll
        for (int i = 0; i < 2; i++) {
            int m0 = wm + i * 16 + (lane >> 2);
            ah[i][0] = Qh[m0*36 + kk+kq];     ah[i][1] = Qh[(m0+8)*36 + kk+kq];
            ah[i][2] = Qh[m0*36 + kk+kq+4];   ah[i][3] = Qh[(m0+8)*36 + kk+kq+4];
            al[i][0] = Ql[m0*36 + kk+kq];     al[i][1] = Ql[(m0+8)*36 + kk+kq];
            al[i][2] = Ql[m0*36 + kk+kq+4];   al[i][3] = Ql[(m0+8)*36 + kk+kq+4];
        }
        #pragma unroll
        for (int j = 0; j < 8; j++) {
            int nb = wn + j * 8 + (lane >> 2);
            unsigned bh2[2] = {Kh[nb*36 + kk+kq], Kh[nb*36 + kk+kq+4]};
            unsigned bl2[2] = {Kl[nb*36 + kk+kq], Kl[nb*36 + kk+kq+4]};
            #pragma unroll
            for (int i = 0; i < 2; i++) {
                mma16(acc[i][j], al[i], bh2);
                mma16(acc[i][j], ah[i], bl2);
                mma16(acc[i][j], ah[i], bh2);
            }
        }
    }

    const int* mrow = mask + (size_t)b * SEQ * SEQ;
    float* out = attn + (size_t)bh_i * SEQ * SEQ;
    float rs[2][2] = {};
    #pragma unroll
    for (int j = 0; j < 8; j++) {
        int c = c0 + wn + j * 8 + (lane & 3) * 2;
        #pragma unroll
        for (int i = 0; i < 2; i++) {
            size_t r = q0 + wm + i * 16 + (lane >> 2);
            int2 m0v = *(const int2*)&mrow[r * SEQ + c];
            int2 m1v = *(const int2*)&mrow[(r + 8) * SEQ + c];
            float2 o0, o1;
            o0.x = m0v.x ? __expf(acc[i][j][0] * 0.125f) : 0.f;
            o0.y = m0v.y ? __expf(acc[i][j][1] * 0.125f) : 0.f;
            o1.x = m1v.x ? __expf(acc[i][j][2] * 0.125f) : 0.f;
            o1.y = m1v.y ? __expf(acc[i][j][3] * 0.125f) : 0.f;
            __stcs((float2*)&out[r * SEQ + c],       o0);
            __stcs((float2*)&out[(r + 8) * SEQ + c], o1);
            rs[i][0] += o0.x + o0.y;
            rs[i][1] += o1.x + o1.y;
        }
    }
    #pragma unroll
    for (int i = 0; i < 2; i++)
        #pragma unroll
        for (int hh = 0; hh < 2; hh++) {
            float v = rs[i][hh];
            v += __shfl_xor_sync(0xffffffffu, v, 1);
            v += __shfl_xor_sync(0xffffffffu, v, 2);
            if ((lane & 3) == 0)
                sums[(warp >> 2) * 128 + wm + i * 16 + hh * 8 + (lane >> 2)] = v;
        }
    __syncthreads();
    if (tid < 128) {
        float tot = sums[tid] + sums[128 + tid];
        partial[((size_t)bh_i * SEQ + q0 + tid) * NKT + blockIdx.y] = tot;
    }
}

// ---------------------------------------------------------------------------
// Fused PV (tf32, split-K=2), cp.async 3-stage, 4 CTAs/SM.
// ---------------------------------------------------------------------------
__global__ __launch_bounds__(256, 4)
void pv_norm(float* __restrict__ attn, const float* __restrict__ gv,
             const float* __restrict__ partial, float* __restrict__ pctx) {
    extern __shared__ float psm[];
    float* Ps    = psm;
    float* Vs    = psm + PV_PS;
    float* inv_s = psm + PV_PS + PV_VS;

    const int tid = threadIdx.x, lane = tid & 31, warp = tid >> 5;
    const int wm = (warp & 3) * 32, wn = (warp >> 2) * 32;
    const int bh_i = blockIdx.z, b = bh_i >> 4, h = bh_i & 15;
    float* P = attn + (size_t)bh_i * SEQ * SEQ;
    const float* V = gv + (size_t)b * SEQ * DMODEL + h * DHEAD;
    float* Cc = pctx + (size_t)blockIdx.x * PS
                     + (size_t)b * SEQ * DMODEL + h * DHEAD;
    const int q0 = blockIdx.y * 128;
    const int kbase = blockIdx.x * (SEQ / SPLITK);
    const int ntiles = (SEQ / SPLITK) / 16;

    auto prefetch = [&](int t) {
        int s = t % PVSTG;
        int k0 = kbase + t * 16;
        #pragma unroll
        for (int l = 0; l < 2; l++) {
            int c = tid + l * 256, r = c >> 2, qd = (c & 3) * 4;
            cpasync16(&Ps[s*2560 + r*20 + qd], &P[(size_t)(q0+r)*SEQ + k0 + qd]);
        }
        {
            int kk = tid >> 4, n = (tid & 15) * 4;
            cpasync16(&Vs[s*1152 + kk*72 + n], &V[(size_t)(k0+kk)*DMODEL + n]);
        }
        asm volatile("cp.async.commit_group;");
    };
    #pragma unroll
    for (int t = 0; t < PVSTG - 1; t++) prefetch(t);

    if (tid < 128) {
        const float4* pp = (const float4*)&partial[((size_t)bh_i * SEQ + q0 + tid) * NKT];
        float4 p0 = pp[0], p1 = pp[1], p2 = pp[2], p3 = pp[3];
        float s = ((p0.x + p0.y) + (p0.z + p0.w)) + ((p1.x + p1.y) + (p1.z + p1.w))
                + ((p2.x + p2.y) + (p2.z + p2.w)) + ((p3.x + p3.y) + (p3.z + p3.w));
        inv_s[tid] = 1.0f / s;
    }

    float acc[2][4][4] = {};
    for (int t = 0; t < ntiles; t++) {
        int s = t % PVSTG;
        asm volatile("cp.async.wait_group %0;" :: "n"(PVSTG - 2));
        __syncthreads();
        const float* Pp = &Ps[s*2560];
        const float* Vp = &Vs[s*1152];
        #pragma unroll
        for (int kk = 0; kk < 16; kk += 8) {
            const int kr = kk + (lane & 3), m0 = wm + (lane >> 2);
            unsigned af[2][4];
            #pragma unroll
            for (int i = 0; i < 2; i++) {
                af[i][0] = __float_as_uint(Pp[(m0+i*16)*20 + kr]);
                af[i][1] = __float_as_uint(Pp[(m0+i*16+8)*20 + kr]);
                af[i][2] = __float_as_uint(Pp[(m0+i*16)*20 + kr+4]);
                af[i][3] = __float_as_uint(Pp[(m0+i*16+8)*20 + kr+4]);
            }
            #pragma unroll
            for (int j = 0; j < 4; j++) {
                int nb = wn + j * 8 + (lane >> 2);
                unsigned bfr[2] = {__float_as_uint(Vp[kr*72 + nb]),
                                   __float_as_uint(Vp[(kr+4)*72 + nb])};
                mma8(acc[0][j], af[0], bfr);
                mma8(acc[1][j], af[1], bfr);
            }
        }
        {
            int k0 = kbase + t * 16;
            #pragma unroll
            for (int l = 0; l < 2; l++) {
                int c = tid + l * 256, r = c >> 2, qd = (c & 3) * 4;
                float4 a4 = *(const float4*)&Pp[r*20 + qd];
                float sc = inv_s[r];
                a4.x *= sc; a4.y *= sc; a4.z *= sc; a4.w *= sc;
                __stcs((float4*)&P[(size_t)(q0+r)*SEQ + k0 + qd], a4);
            }
        }
        __syncthreads();
        if (t + PVSTG - 1 < ntiles) prefetch(t + PVSTG - 1);
        else asm volatile("cp.async.commit_group;");
    }
    #pragma unroll
    for (int j = 0; j < 4; j++) {
        int c = wn + j * 8 + (lane & 3) * 2;
        #pragma unroll
        for (int i = 0; i < 2; i++) {
            int rl = wm + i * 16 + (lane >> 2);
            float sc0 = inv_s[rl], sc1 = inv_s[rl + 8];
            size_t r = q0 + rl;
            float2 o0 = {acc[i][j][0] * sc0, acc[i][j][1] * sc0};
            float2 o1 = {acc[i][j][2] * sc1, acc[i][j][3] * sc1};
            *(float2*)&Cc[r * DMODEL + c]       = o0;
            *(float2*)&Cc[(r + 8) * DMODEL + c] = o1;
        }
    }
}

// ---------------------------------------------------------------------------
// Residual + LayerNorm.
// ---------------------------------------------------------------------------
__global__ void ln_kernel(const float* __restrict__ resid,
                          const float* __restrict__ x,
                          const float* __restrict__ gamma,
                          const float* __restrict__ beta,
                          float* __restrict__ out) {
    const size_t row = blockIdx.x;
    const float4* xr = reinterpret_cast<const float4*>(x + row * DMODEL);
    const float4* rr = reinterpret_cast<const float4*>(resid + row * DMODEL);
    const int t = threadIdx.x;
    __shared__ float sred[8];

    float4 a = rr[t], bv = xr[t];
    float4 v = {a.x + bv.x, a.y + bv.y, a.z + bv.z, a.w + bv.w};
    float s = v.x + v.y + v.z + v.w;
    #pragma unroll
    for (int o = 16; o > 0; o >>= 1) s += __shfl_xor_sync(0xffffffffu, s, o);
    if ((t & 31) == 0) sred[t >> 5] = s;
    __syncthreads();
    float tot = 0.f;
    #pragma unroll
    for (int i = 0; i < 8; i++) tot += sred[i];
    const float mu = tot * (1.0f / DMODEL);
    __syncthreads();

    float dx = v.x - mu, dy = v.y - mu, dz = v.z - mu, dw = v.w - mu;
    float sq = dx*dx + dy*dy + dz*dz + dw*dw;
    #pragma unroll
    for (int o = 16; o > 0; o >>= 1) sq += __shfl_xor_sync(0xffffffffu, sq, o);
    if ((t & 31) == 0) sred[t >> 5] = sq;
    __syncthreads();
    float tot2 = 0.f;
    #pragma unroll
    for (int i = 0; i < 8; i++) tot2 += sred[i];
    const float inv = rsqrtf(tot2 * (1.0f / DMODEL) + 1e-5f);

    float4 g = reinterpret_cast<const float4*>(gamma)[t];
    float4 be = reinterpret_cast<const float4*>(beta)[t];
    float4 o;
    o.x = dx * inv * g.x + be.x;
    o.y = dy * inv * g.y + be.y;
    o.z = dz * inv * g.z + be.z;
    o.w = dw * inv * g.w + be.w;
    reinterpret_cast<float4*>(out + row * DMODEL)[t] = o;
}

// ---------------------------------------------------------------------------
extern "C" void kernel_launch(void* const* d_in, const int* in_sizes, int n_in,
                              void* d_out, int out_size) {
    const float* q     = (const float*)d_in[0];
    const float* k     = (const float*)d_in[1];
    const float* v     = (const float*)d_in[2];
    const int*   mask  = (const int*)  d_in[3];
    const float* wq    = (const float*)d_in[4];
    const float* bq    = (const float*)d_in[5];
    const float* wk    = (const float*)d_in[6];
    const float* bk    = (const float*)d_in[7];
    const float* wv    = (const float*)d_in[8];
    const float* bv    = (const float*)d_in[9];
    const float* wo    = (const float*)d_in[10];
    const float* bo    = (const float*)d_in[11];
    const float* gamma = (const float*)d_in[12];
    const float* beta  = (const float*)d_in[13];

    float* out  = (float*)d_out;
    float* attn = out + ATT_OFF;

    void* sp = nullptr;
    cudaGetSymbolAddress(&sp, g_scratch);
    float* gv      = (float*)sp;
    float* go      = gv + PS;
    float* pctx    = go + PS;                 // SPLITK x PS
    float* partial = pctx + SPLITK * PS;
    unsigned* ipk  = (unsigned*)(partial + PARTIAL_SZ);   // q hi/lo, k hi/lo (4*PKA)
    unsigned* wpk  = ipk + 4 * PKA;                        // wq hi/lo, wk hi/lo (4*PKW)
    unsigned* opk  = wpk + 4 * PKW;                        // gq hi/lo, gk hi/lo (4*PKA)

    cudaFuncSetAttribute(scores_exp,   cudaFuncAttributeMaxDynamicSharedMemorySize, SC_SMEM);
    cudaFuncSetAttribute(pv_norm,      cudaFuncAttributeMaxDynamicSharedMemorySize, PV_SMEM);
    cudaFuncSetAttribute(gemm_nt_tf32, cudaFuncAttributeMaxDynamicSharedMemorySize, VP_SMEM);
    cudaFuncSetAttribute(gemm_o_tf32,  cudaFuncAttributeMaxDynamicSharedMemorySize, OP_SMEM);
    cudaFuncSetAttribute(gemm_qk_pk,   cudaFuncAttributeMaxDynamicSharedMemorySize, QK_SMEM);

    // Prepack q, k, wq, wk into bf16 (hi,lo) kpair arrays.
    prepack<<<(int)(PKA/2 + 255)/256, 256>>>(q,  ipk,            ipk + PKA,     (int)PKA);
    prepack<<<(int)(PKA/2 + 255)/256, 256>>>(k,  ipk + 2*PKA,    ipk + 3*PKA,   (int)PKA);
    prepack<<<(int)(PKW/2 + 255)/256, 256>>>(wq, wpk,            wpk + PKW,     (int)PKW);
    prepack<<<(int)(PKW/2 + 255)/256, 256>>>(wk, wpk + 2*PKW,    wpk + 3*PKW,   (int)PKW);

    dim3 gQK(DMODEL / 128, MROWS / 128, 2);             // (8, 32, 2)
    gemm_qk_pk<<<gQK, 256, QK_SMEM>>>(ipk, wpk, bq, bk, opk);

    dim3 gProj(DMODEL / 128, MROWS / 128);              // (8, 32)
    gemm_nt_tf32<<<gProj, 256, VP_SMEM>>>(v, wv, bv, gv);

    dim3 gScores(BATCH * NHEADS, NKT, SEQ / 128);       // (32, 16, 16)
    scores_exp<<<gScores, 256, SC_SMEM>>>(opk, mask, attn, partial);

    dim3 gPV(SPLITK, SEQ / 128, BATCH * NHEADS);        // (2, 16, 32)
    pv_norm<<<gPV, 256, PV_SMEM>>>(attn, gv, partial, pctx);

    gemm_o_tf32<<<gProj, 256, OP_SMEM>>>(pctx, wo, bo, go);

    ln_kernel<<<MROWS, 256>>>(q, go, gamma, beta, out);
}